// round 1
// baseline (speedup 1.0000x reference)
#include <cuda_runtime.h>
#include <math.h>

#define NN 50000
#define EE 800000
#define TT 2

// ---------------- scratch (static device globals; no allocation) ----------------
__device__ float  g_fh[(size_t)TT * NN * 128];   // projected features per type
__device__ float4 g_el[TT * NN];                 // per-node left attn logits (4 heads)
__device__ float4 g_er[TT * NN];                 // per-node right attn logits
__device__ int    g_deg[TT * NN];
__device__ int    g_start[TT * NN];
__device__ int    g_cnt[TT * NN];
__device__ int    g_col[TT * EE];                // CSR-by-dst: src ids

// ---------------- helpers ----------------
__device__ __forceinline__ float lrelu(float x) { return x > 0.f ? x : 0.2f * x; }

__device__ __forceinline__ float wsum(float v) {
#pragma unroll
    for (int o = 16; o > 0; o >>= 1) v += __shfl_xor_sync(0xffffffffu, v, o);
    return v;
}
__device__ __forceinline__ float wmax(float v) {
#pragma unroll
    for (int o = 16; o > 0; o >>= 1) v = fmaxf(v, __shfl_xor_sync(0xffffffffu, v, o));
    return v;
}

// ---------------- kernels ----------------
__global__ void init_kernel() {
    int i = blockIdx.x * blockDim.x + threadIdx.x;
    if (i < TT * NN) { g_deg[i] = 0; g_cnt[i] = 0; }
}

// fh[t] = feature @ W[t]   (128x128 output tile per block, 8x8 microtile)
__global__ void gemm_kernel(const float* __restrict__ feat, const float* __restrict__ W) {
    __shared__ float As[128][36];   // rows x k-tile(32), padded for alignment/banks
    __shared__ float Bs[32][128];   // k-tile x cols
    const int t   = blockIdx.y;
    const int m0  = blockIdx.x * 128;
    const int tid = threadIdx.x;
    const int tx  = tid & 15;       // 16 col groups
    const int ty  = tid >> 4;       // 16 row groups
    const float* Wt = W + t * 16384;

    float c[8][8];
#pragma unroll
    for (int i = 0; i < 8; i++)
#pragma unroll
        for (int j = 0; j < 8; j++) c[i][j] = 0.f;

    for (int kt = 0; kt < 128; kt += 32) {
        // load A tile: 128 rows x 32 cols (float4 per thread x4)
#pragma unroll
        for (int i = 0; i < 4; i++) {
            int q   = tid + i * 256;     // 0..1023
            int row = q >> 3;            // 0..127
            int kc  = (q & 7) * 4;       // 0..28
            int gr  = m0 + row;
            float4 v = (gr < NN) ? *(const float4*)(feat + (size_t)gr * 128 + kt + kc)
                                 : make_float4(0.f, 0.f, 0.f, 0.f);
            *(float4*)&As[row][kc] = v;
        }
        // load B tile: 32 x 128
#pragma unroll
        for (int i = 0; i < 4; i++) {
            int q  = tid + i * 256;
            int k  = q >> 5;             // 0..31
            int jc = (q & 31) * 4;       // 0..124
            *(float4*)&Bs[k][jc] = *(const float4*)(Wt + (size_t)(kt + k) * 128 + jc);
        }
        __syncthreads();

#pragma unroll
        for (int k4 = 0; k4 < 32; k4 += 4) {
            float4 a4[8];
#pragma unroll
            for (int i = 0; i < 8; i++) a4[i] = *(const float4*)&As[ty * 8 + i][k4];
#pragma unroll
            for (int s = 0; s < 4; s++) {
                float b[8];
                *(float4*)&b[0] = *(const float4*)&Bs[k4 + s][tx * 8];
                *(float4*)&b[4] = *(const float4*)&Bs[k4 + s][tx * 8 + 4];
#pragma unroll
                for (int i = 0; i < 8; i++) {
                    float av = (s == 0) ? a4[i].x : (s == 1) ? a4[i].y : (s == 2) ? a4[i].z : a4[i].w;
#pragma unroll
                    for (int j = 0; j < 8; j++) c[i][j] = fmaf(av, b[j], c[i][j]);
                }
            }
        }
        __syncthreads();
    }

#pragma unroll
    for (int i = 0; i < 8; i++) {
        int gr = m0 + ty * 8 + i;
        if (gr < NN) {
            float* o = g_fh + ((size_t)t * NN + gr) * 128 + tx * 8;
            *(float4*)o       = make_float4(c[i][0], c[i][1], c[i][2], c[i][3]);
            *(float4*)(o + 4) = make_float4(c[i][4], c[i][5], c[i][6], c[i][7]);
        }
    }
}

// el/er = head-wise dot(fh, attn_l/r). One warp per node.
__global__ void elr_kernel(const float* __restrict__ al, const float* __restrict__ ar) {
    int lane = threadIdx.x & 31;
    int n    = blockIdx.x * (blockDim.x >> 5) + (threadIdx.x >> 5);
    int t    = blockIdx.y;
    if (n >= NN) return;
    const float* f = g_fh + ((size_t)t * NN + n) * 128 + lane;
    float pl[4], pr[4];
#pragma unroll
    for (int k = 0; k < 4; k++) {
        float v = f[32 * k];
        pl[k] = v * al[t * 128 + lane + 32 * k];
        pr[k] = v * ar[t * 128 + lane + 32 * k];
    }
#pragma unroll
    for (int k = 0; k < 4; k++) { pl[k] = wsum(pl[k]); pr[k] = wsum(pr[k]); }
    if (lane == 0) {
        g_el[t * NN + n] = make_float4(pl[0], pl[1], pl[2], pl[3]);
        g_er[t * NN + n] = make_float4(pr[0], pr[1], pr[2], pr[3]);
    }
}

__global__ void hist_kernel(const int* __restrict__ dst) {
    int i = blockIdx.x * blockDim.x + threadIdx.x;
    int t = blockIdx.y;
    if (i < EE) atomicAdd(&g_deg[t * NN + dst[t * EE + i]], 1);
}

// exclusive scan of degrees -> start offsets. One block per type.
__global__ void scan_kernel() {
    __shared__ int sm[1024];
    int t = blockIdx.x;
    const int* deg = &g_deg[t * NN];
    int* st = &g_start[t * NN];
    int tid = threadIdx.x;
    const int C = (NN + 1023) / 1024;   // 49
    int base = tid * C;
    int s = 0;
    for (int i = 0; i < C; i++) { int idx = base + i; if (idx < NN) s += deg[idx]; }
    sm[tid] = s;
    __syncthreads();
    for (int off = 1; off < 1024; off <<= 1) {
        int v = (tid >= off) ? sm[tid - off] : 0;
        __syncthreads();
        sm[tid] += v;
        __syncthreads();
    }
    int run = sm[tid] - s;   // exclusive prefix
    for (int i = 0; i < C; i++) {
        int idx = base + i;
        if (idx < NN) { st[idx] = run; run += deg[idx]; }
    }
}

__global__ void scatter_kernel(const int* __restrict__ src, const int* __restrict__ dst) {
    int i = blockIdx.x * blockDim.x + threadIdx.x;
    int t = blockIdx.y;
    if (i >= EE) return;
    int d = dst[t * EE + i];
    int p = g_start[t * NN + d] + atomicAdd(&g_cnt[t * NN + d], 1);
    g_col[t * EE + p] = src[t * EE + i];
}

// fused: per-node online-softmax attention + aggregation + bias + LayerNorm + ELU.
// One warp per (node, type). Lane l owns output elements l, l+32, l+64, l+96 (head = k).
__global__ void attn_kernel(const float* __restrict__ bias, const float* __restrict__ lnw,
                            const float* __restrict__ lnb, float* __restrict__ out) {
    const float NEG_INF = __int_as_float(0xff800000);
    int lane = threadIdx.x & 31;
    int n    = blockIdx.x * (blockDim.x >> 5) + (threadIdx.x >> 5);
    int t    = blockIdx.y;
    if (n >= NN) return;
    int base = t * NN + n;

    float4 er4 = g_er[base];
    int beg = g_start[base];
    int end = beg + g_deg[base];

    const float* fhT  = g_fh + (size_t)t * NN * 128;
    const int*   colT = g_col + t * EE;

    float m0 = NEG_INF, m1 = NEG_INF, m2 = NEG_INF, m3 = NEG_INF;
    float s0 = 0.f, s1 = 0.f, s2 = 0.f, s3 = 0.f;
    float a0 = 0.f, a1 = 0.f, a2 = 0.f, a3 = 0.f;

    for (int c = beg; c < end; c += 32) {
        int i = c + lane;
        bool v = (i < end);
        int sI = v ? colT[i] : 0;
        float e0, e1, e2, e3;
        if (v) {
            float4 el4 = g_el[t * NN + sI];
            e0 = lrelu(el4.x + er4.x);
            e1 = lrelu(el4.y + er4.y);
            e2 = lrelu(el4.z + er4.z);
            e3 = lrelu(el4.w + er4.w);
        } else {
            e0 = e1 = e2 = e3 = NEG_INF;
        }
        float nm0 = fmaxf(m0, wmax(e0));
        float nm1 = fmaxf(m1, wmax(e1));
        float nm2 = fmaxf(m2, wmax(e2));
        float nm3 = fmaxf(m3, wmax(e3));
        float r0 = __expf(m0 - nm0), r1 = __expf(m1 - nm1);
        float r2 = __expf(m2 - nm2), r3 = __expf(m3 - nm3);
        float w0 = v ? __expf(e0 - nm0) : 0.f;
        float w1 = v ? __expf(e1 - nm1) : 0.f;
        float w2 = v ? __expf(e2 - nm2) : 0.f;
        float w3 = v ? __expf(e3 - nm3) : 0.f;
        s0 = s0 * r0 + wsum(w0);
        s1 = s1 * r1 + wsum(w1);
        s2 = s2 * r2 + wsum(w2);
        s3 = s3 * r3 + wsum(w3);
        a0 *= r0; a1 *= r1; a2 *= r2; a3 *= r3;
        m0 = nm0; m1 = nm1; m2 = nm2; m3 = nm3;

        int cnt = min(32, end - c);
        for (int q = 0; q < cnt; q++) {
            int sq    = __shfl_sync(0xffffffffu, sI, q);
            float w0q = __shfl_sync(0xffffffffu, w0, q);
            float w1q = __shfl_sync(0xffffffffu, w1, q);
            float w2q = __shfl_sync(0xffffffffu, w2, q);
            float w3q = __shfl_sync(0xffffffffu, w3, q);
            const float* f = fhT + (size_t)sq * 128 + lane;
            a0 = fmaf(w0q, f[0],  a0);
            a1 = fmaf(w1q, f[32], a1);
            a2 = fmaf(w2q, f[64], a2);
            a3 = fmaf(w3q, f[96], a3);
        }
    }

    float i0 = s0 > 0.f ? 1.f / s0 : 0.f;
    float i1 = s1 > 0.f ? 1.f / s1 : 0.f;
    float i2 = s2 > 0.f ? 1.f / s2 : 0.f;
    float i3 = s3 > 0.f ? 1.f / s3 : 0.f;
    float x0 = a0 * i0 + bias[t * 128 + lane];
    float x1 = a1 * i1 + bias[t * 128 + lane + 32];
    float x2 = a2 * i2 + bias[t * 128 + lane + 64];
    float x3 = a3 * i3 + bias[t * 128 + lane + 96];

    float mean = wsum(x0 + x1 + x2 + x3) * (1.f / 128.f);
    float d0 = x0 - mean, d1 = x1 - mean, d2 = x2 - mean, d3 = x3 - mean;
    float var = wsum(d0 * d0 + d1 * d1 + d2 * d2 + d3 * d3) * (1.f / 128.f);
    float rinv = rsqrtf(var + 1e-12f);

    float y0 = lnw[t * 128 + lane]      * (d0 * rinv) + lnb[t * 128 + lane];
    float y1 = lnw[t * 128 + lane + 32] * (d1 * rinv) + lnb[t * 128 + lane + 32];
    float y2 = lnw[t * 128 + lane + 64] * (d2 * rinv) + lnb[t * 128 + lane + 64];
    float y3 = lnw[t * 128 + lane + 96] * (d3 * rinv) + lnb[t * 128 + lane + 96];
    y0 = y0 > 0.f ? y0 : __expf(y0) - 1.f;
    y1 = y1 > 0.f ? y1 : __expf(y1) - 1.f;
    y2 = y2 > 0.f ? y2 : __expf(y2) - 1.f;
    y3 = y3 > 0.f ? y3 : __expf(y3) - 1.f;

    float* o = out + (size_t)n * (TT * 128) + t * 128 + lane;
    o[0]  = y0;
    o[32] = y1;
    o[64] = y2;
    o[96] = y3;
}

// ---------------- launch ----------------
extern "C" void kernel_launch(void* const* d_in, const int* in_sizes, int n_in,
                              void* d_out, int out_size) {
    const float* feature = (const float*)d_in[0];
    const int*   src     = (const int*)d_in[1];
    const int*   dst     = (const int*)d_in[2];
    const float* W       = (const float*)d_in[3];
    const float* al      = (const float*)d_in[4];
    const float* ar      = (const float*)d_in[5];
    const float* bias    = (const float*)d_in[6];
    const float* lnw     = (const float*)d_in[7];
    const float* lnb     = (const float*)d_in[8];
    float* out = (float*)d_out;

    init_kernel<<<(TT * NN + 255) / 256, 256>>>();
    gemm_kernel<<<dim3((NN + 127) / 128, TT), 256>>>(feature, W);
    elr_kernel<<<dim3((NN + 7) / 8, TT), 256>>>(al, ar);
    hist_kernel<<<dim3((EE + 255) / 256, TT), 256>>>(dst);
    scan_kernel<<<TT, 1024>>>();
    scatter_kernel<<<dim3((EE + 255) / 256, TT), 256>>>(src, dst);
    attn_kernel<<<dim3((NN + 7) / 8, TT), 256>>>(bias, lnw, lnb, out);
}